// round 11
// baseline (speedup 1.0000x reference)
#include <cuda_runtime.h>
#include <math.h>
#include <stdint.h>

#define N_NODES 10000
#define E_EDGES 320000
#define E_TOT   330000   // + self loops
#define HID     256
#define DOUT    32

// ---------------- scratch (device globals) ----------------
__device__ float g_hidden[N_NODES * HID];
__device__ float g_xl0[N_NODES * HID];
__device__ float g_xr0[N_NODES * HID];
__device__ float g_h1[N_NODES * HID];
__device__ float g_xl1[N_NODES * DOUT];
__device__ float g_xr1[N_NODES * DOUT];
__device__ float g_wcat0[HID * (2 * HID)];   // [256 x 512]
__device__ float g_wcat1[HID * (2 * DOUT)];  // [256 x 64]
__device__ float g_bcat0[2 * HID];
__device__ float g_bcat1[2 * DOUT];
__device__ int   g_count[N_NODES];
__device__ int   g_off[N_NODES + 1];
__device__ int   g_cursor[N_NODES];
__device__ int2  g_edge[E_TOT];              // packed (src, ea-bits)
__device__ float g_ea_part[64];
__device__ float g_ea_mean;

// ---------------- streams/events for fork-join (created at load) ----------------
struct StreamHolder {
    cudaStream_t s, s2;
    cudaEvent_t ef, ej, ep;
    StreamHolder() {
        cudaStreamCreateWithFlags(&s, cudaStreamNonBlocking);
        cudaStreamCreateWithFlags(&s2, cudaStreamNonBlocking);
        cudaEventCreateWithFlags(&ef, cudaEventDisableTiming);
        cudaEventCreateWithFlags(&ej, cudaEventDisableTiming);
        cudaEventCreateWithFlags(&ep, cudaEventDisableTiming);
    }
};
static StreamHolder g_sh;

// ---------------- helpers ----------------
__device__ __forceinline__ float lrelu(float v) { return v > 0.f ? v : 0.2f * v; }

__device__ __forceinline__ float warp_sum(float v) {
    #pragma unroll
    for (int o = 16; o > 0; o >>= 1) v += __shfl_xor_sync(0xffffffffu, v, o);
    return v;
}

__device__ __forceinline__ uint32_t f2tf32(float x) {
    uint32_t r;
    asm("cvt.rna.tf32.f32 %0, %1;" : "=r"(r) : "f"(x));
    return r;
}

__device__ __forceinline__ void mma_tf32(float* c, const uint32_t* a, uint32_t b0, uint32_t b1) {
    asm volatile(
        "mma.sync.aligned.m16n8k8.row.col.f32.tf32.tf32.f32 "
        "{%0,%1,%2,%3},{%4,%5,%6,%7},{%8,%9},{%0,%1,%2,%3};"
        : "+f"(c[0]), "+f"(c[1]), "+f"(c[2]), "+f"(c[3])
        : "r"(a[0]), "r"(a[1]), "r"(a[2]), "r"(a[3]), "r"(b0), "r"(b1));
}

// ---------------- prep: concat weights/biases ----------------
__global__ void k_prep(const float* __restrict__ Wl0, const float* __restrict__ Wr0,
                       const float* __restrict__ bl0, const float* __restrict__ br0,
                       const float* __restrict__ Wl1, const float* __restrict__ Wr1,
                       const float* __restrict__ bl1, const float* __restrict__ br1) {
    int i = blockIdx.x * blockDim.x + threadIdx.x;
    int stride = gridDim.x * blockDim.x;
    for (int idx = i; idx < HID * 2 * HID; idx += stride) {
        int r = idx >> 9, c = idx & 511;
        g_wcat0[idx] = (c < HID) ? Wl0[r * HID + c] : Wr0[r * HID + c - HID];
    }
    for (int idx = i; idx < HID * 2 * DOUT; idx += stride) {
        int r = idx >> 6, c = idx & 63;
        g_wcat1[idx] = (c < DOUT) ? Wl1[r * DOUT + c] : Wr1[r * DOUT + c - DOUT];
    }
    if (i < 2 * HID) g_bcat0[i] = (i < HID) ? bl0[i] : br0[i - HID];
    if (i < 2 * DOUT) g_bcat1[i] = (i < DOUT) ? bl1[i] : br1[i - DOUT];
}

// ---------------- CSR branch: init counts + per-block edge_attr partial sums ----------------
__global__ void k_init_ea(const float* __restrict__ ea) {
    __shared__ float sh[8];
    int i = blockIdx.x * blockDim.x + threadIdx.x;
    int stride = gridDim.x * blockDim.x;
    for (int j = i; j < N_NODES; j += stride) g_count[j] = 1;
    float s = 0.f;
    for (int j = i; j < E_EDGES; j += stride) s += ea[j];
    s = warp_sum(s);
    int lane = threadIdx.x & 31, wid = threadIdx.x >> 5;
    if (lane == 0) sh[wid] = s;
    __syncthreads();
    if (wid == 0) {
        s = (lane < (blockDim.x >> 5)) ? sh[lane] : 0.f;
        s = warp_sum(s);
        if (lane == 0) g_ea_part[blockIdx.x] = s;
    }
}

// ---------------- histogram by dst ----------------
__global__ void k_hist(const int* __restrict__ ei) {
    int e = blockIdx.x * blockDim.x + threadIdx.x;
    if (e < E_EDGES) atomicAdd(&g_count[ei[E_EDGES + e]], 1);
}

// ---------------- 1-block scan of offsets + ea-mean reduce ----------------
__global__ void k_scan() {
    __shared__ int warp_tot[32];
    const int t = threadIdx.x;
    const int lane = t & 31, wid = t >> 5;
    const int CH = 10;
    int base = t * CH;
    int local[CH];
    int s = 0;
    #pragma unroll
    for (int i = 0; i < CH; i++) {
        int idx = base + i;
        int v = (idx < N_NODES) ? g_count[idx] : 0;
        local[i] = s;
        s += v;
    }
    int x = s;
    #pragma unroll
    for (int o = 1; o < 32; o <<= 1) {
        int y = __shfl_up_sync(0xffffffffu, x, o);
        if (lane >= o) x += y;
    }
    if (lane == 31) warp_tot[wid] = x;
    __syncthreads();
    if (wid == 0) {
        int w = warp_tot[lane];
        #pragma unroll
        for (int o = 1; o < 32; o <<= 1) {
            int y = __shfl_up_sync(0xffffffffu, w, o);
            if (lane >= o) w += y;
        }
        warp_tot[lane] = w;
    }
    if (wid == 1) {
        float v = g_ea_part[lane] + g_ea_part[lane + 32];
        v = warp_sum(v);
        if (lane == 0) g_ea_mean = v * (1.f / (float)E_EDGES);
    }
    __syncthreads();
    int pre = x - s + (wid > 0 ? warp_tot[wid - 1] : 0);
    #pragma unroll
    for (int i = 0; i < CH; i++) {
        int idx = base + i;
        if (idx <= N_NODES) g_off[idx] = pre + local[i];
    }
}

// ---------------- parallel self-loop placement + cursor init ----------------
__global__ void k_selfloop() {
    int i = blockIdx.x * blockDim.x + threadIdx.x;
    if (i >= N_NODES) return;
    float eam = g_ea_mean;
    int off = g_off[i];
    g_edge[off] = make_int2(i, __float_as_int(eam));
    g_cursor[i] = off + 1;
}

// ---------------- scatter real edges into CSR-by-dst (packed int2) ----------------
__global__ void k_scatter(const int* __restrict__ ei, const float* __restrict__ eattr) {
    int e = blockIdx.x * blockDim.x + threadIdx.x;
    if (e >= E_EDGES) return;
    int src = ei[e], dst = ei[E_EDGES + e];
    int pos = atomicAdd(&g_cursor[dst], 1);
    g_edge[pos] = make_int2(src, __float_as_int(eattr[e]));
}

// ---------------- tf32 tensor-core GEMM: C = A[M,K] @ B[K,Nc] + bias ----------------
template<bool SPLIT>
__global__ void mma_gemm(const float* __restrict__ A, const float* __restrict__ B,
                         const float* __restrict__ bias,
                         float* __restrict__ C0, float* __restrict__ C1,
                         int M, int Nc, int K) {
    constexpr int BM = 128, BN = 64, BK = 32;
    constexpr int NT = 256;
    constexpr int NA = BM * BK / 4 / NT;
    constexpr int NB = BK * BN / 4 / NT;
    __shared__ uint32_t As[BM][BK + 4];
    __shared__ uint32_t Bs[BK][BN + 4];

    const int tid = threadIdx.x;
    const int wid = tid >> 5;
    const int lane = tid & 31;
    const int gid = lane >> 2;
    const int tg  = lane & 3;
    const int wm = (wid & 3) * 32;
    const int wn = (wid >> 2) * 32;
    const int row0 = blockIdx.y * BM, col0 = blockIdx.x * BN;

    float acc[2][4][4];
    #pragma unroll
    for (int mt = 0; mt < 2; mt++)
        #pragma unroll
        for (int nt = 0; nt < 4; nt++)
            #pragma unroll
            for (int i = 0; i < 4; i++) acc[mt][nt][i] = 0.f;

    float4 ra[NA], rb[NB];

    auto g2r = [&](int k0) {
        #pragma unroll
        for (int i = 0; i < NA; i++) {
            int lin = (tid + i * NT) * 4;
            int r = lin / BK, c = lin % BK;
            int gr = row0 + r;
            ra[i] = (gr < M) ? *(const float4*)&A[(size_t)gr * K + k0 + c]
                             : make_float4(0.f, 0.f, 0.f, 0.f);
        }
        #pragma unroll
        for (int i = 0; i < NB; i++) {
            int lin = (tid + i * NT) * 4;
            int kr = lin / BN, c = lin % BN;
            rb[i] = *(const float4*)&B[(size_t)(k0 + kr) * Nc + col0 + c];
        }
    };
    auto r2s = [&]() {
        #pragma unroll
        for (int i = 0; i < NA; i++) {
            int lin = (tid + i * NT) * 4;
            int r = lin / BK, c = lin % BK;
            As[r][c + 0] = f2tf32(ra[i].x); As[r][c + 1] = f2tf32(ra[i].y);
            As[r][c + 2] = f2tf32(ra[i].z); As[r][c + 3] = f2tf32(ra[i].w);
        }
        #pragma unroll
        for (int i = 0; i < NB; i++) {
            int lin = (tid + i * NT) * 4;
            int kr = lin / BN, c = lin % BN;
            Bs[kr][c + 0] = f2tf32(rb[i].x); Bs[kr][c + 1] = f2tf32(rb[i].y);
            Bs[kr][c + 2] = f2tf32(rb[i].z); Bs[kr][c + 3] = f2tf32(rb[i].w);
        }
    };

    g2r(0);
    r2s();
    __syncthreads();

    const int NTILES = K / BK;
    for (int t = 0; t < NTILES; t++) {
        if (t + 1 < NTILES) g2r((t + 1) * BK);
        #pragma unroll
        for (int ks = 0; ks < BK; ks += 8) {
            uint32_t af[2][4];
            #pragma unroll
            for (int mt = 0; mt < 2; mt++) {
                int r0 = wm + mt * 16 + gid;
                af[mt][0] = As[r0][ks + tg];
                af[mt][1] = As[r0 + 8][ks + tg];
                af[mt][2] = As[r0][ks + tg + 4];
                af[mt][3] = As[r0 + 8][ks + tg + 4];
            }
            #pragma unroll
            for (int nt = 0; nt < 4; nt++) {
                int cn = wn + nt * 8 + gid;
                uint32_t b0 = Bs[ks + tg][cn];
                uint32_t b1 = Bs[ks + tg + 4][cn];
                #pragma unroll
                for (int mt = 0; mt < 2; mt++)
                    mma_tf32(acc[mt][nt], af[mt], b0, b1);
            }
        }
        if (t + 1 < NTILES) {
            __syncthreads();
            r2s();
            __syncthreads();
        }
    }

    const int S = Nc >> 1;
    #pragma unroll
    for (int mt = 0; mt < 2; mt++) {
        int gr0 = row0 + wm + mt * 16 + gid;
        int gr1 = gr0 + 8;
        #pragma unroll
        for (int nt = 0; nt < 4; nt++) {
            int gc = col0 + wn + nt * 8 + tg * 2;
            float b0 = bias[gc], b1 = bias[gc + 1];
            float v00 = acc[mt][nt][0] + b0, v01 = acc[mt][nt][1] + b1;
            float v10 = acc[mt][nt][2] + b0, v11 = acc[mt][nt][3] + b1;
            if (SPLIT) {
                if (gr0 < M) {
                    if (gc < S) { C0[(size_t)gr0 * S + gc] = v00; } else { C1[(size_t)gr0 * S + gc - S] = v00; }
                    if (gc + 1 < S) { C0[(size_t)gr0 * S + gc + 1] = v01; } else { C1[(size_t)gr0 * S + gc + 1 - S] = v01; }
                }
                if (gr1 < M) {
                    if (gc < S) { C0[(size_t)gr1 * S + gc] = v10; } else { C1[(size_t)gr1 * S + gc - S] = v10; }
                    if (gc + 1 < S) { C0[(size_t)gr1 * S + gc + 1] = v11; } else { C1[(size_t)gr1 * S + gc + 1 - S] = v11; }
                }
            } else {
                if (gr0 < M) *(float2*)&C0[(size_t)gr0 * Nc + gc] = make_float2(v00, v01);
                if (gr1 < M) *(float2*)&C0[(size_t)gr1 * Nc + gc] = make_float2(v10, v11);
            }
        }
    }
}

// ---------------- fused layer-0: online-softmax GAT, 4-edge unroll ----------------
__global__ void k_node0(const float* __restrict__ We, const float* __restrict__ att,
                        const float* __restrict__ bias0, const float* __restrict__ g0,
                        const float* __restrict__ be0) {
    int r = blockIdx.x * (blockDim.x >> 5) + (threadIdx.x >> 5);
    if (r >= N_NODES) return;
    int lane = threadIdx.x & 31;
    int idx0 = lane * 2, idx1 = lane * 2 + 1;

    const float4* xl4 = (const float4*)g_xl0;
    const float4* xr4 = (const float4*)g_xr0;
    const float4* We4 = (const float4*)We;
    const float4* at4 = (const float4*)att;

    float4 xra = xr4[r * 64 + idx0], xrb = xr4[r * 64 + idx1];
    float4 wea = We4[idx0],          web = We4[idx1];
    float4 ata = at4[idx0],          atb = at4[idx1];

    const float NINF = __int_as_float(0xFF800000);
    float m = NINF, s = 0.f;
    float4 accA = make_float4(0.f, 0.f, 0.f, 0.f);
    float4 accB = make_float4(0.f, 0.f, 0.f, 0.f);

    const int beg = g_off[r], end = g_off[r + 1];
    const int cnt = end - beg;

    #define LOGIT(a, b, ea)                                              \
        (lrelu((a).x + xra.x + (ea) * wea.x) * ata.x                     \
       + lrelu((a).y + xra.y + (ea) * wea.y) * ata.y                     \
       + lrelu((a).z + xra.z + (ea) * wea.z) * ata.z                     \
       + lrelu((a).w + xra.w + (ea) * wea.w) * ata.w                     \
       + lrelu((b).x + xrb.x + (ea) * web.x) * atb.x                     \
       + lrelu((b).y + xrb.y + (ea) * web.y) * atb.y                     \
       + lrelu((b).z + xrb.z + (ea) * web.z) * atb.z                     \
       + lrelu((b).w + xrb.w + (ea) * web.w) * atb.w)

    #define ONLINE_UPD(p, a, b)                                           \
        do {                                                              \
            if ((p) > m) {                                                \
                float c_ = __expf(m - (p));                               \
                s *= c_;                                                  \
                accA.x *= c_; accA.y *= c_; accA.z *= c_; accA.w *= c_;   \
                accB.x *= c_; accB.y *= c_; accB.z *= c_; accB.w *= c_;   \
                m = (p);                                                  \
            }                                                             \
            float w_ = __expf((p) - m);                                   \
            s += w_;                                                      \
            accA.x += w_ * (a).x; accA.y += w_ * (a).y;                   \
            accA.z += w_ * (a).z; accA.w += w_ * (a).w;                   \
            accB.x += w_ * (b).x; accB.y += w_ * (b).y;                   \
            accB.z += w_ * (b).z; accB.w += w_ * (b).w;                   \
        } while (0)

    int j = 0;
    for (; j + 3 < cnt; j += 4) {
        int2 ed0 = g_edge[beg + j],     ed1 = g_edge[beg + j + 1];
        int2 ed2 = g_edge[beg + j + 2], ed3 = g_edge[beg + j + 3];
        float e0 = __int_as_float(ed0.y), e1 = __int_as_float(ed1.y);
        float e2 = __int_as_float(ed2.y), e3 = __int_as_float(ed3.y);
        // 8 independent gathers in flight
        float4 a0 = xl4[ed0.x * 64 + idx0];
        float4 b0 = xl4[ed0.x * 64 + idx1];
        float4 a1 = xl4[ed1.x * 64 + idx0];
        float4 b1 = xl4[ed1.x * 64 + idx1];
        float4 a2 = xl4[ed2.x * 64 + idx0];
        float4 b2 = xl4[ed2.x * 64 + idx1];
        float4 a3 = xl4[ed3.x * 64 + idx0];
        float4 b3 = xl4[ed3.x * 64 + idx1];

        float p0 = LOGIT(a0, b0, e0);
        float p1 = LOGIT(a1, b1, e1);
        float p2 = LOGIT(a2, b2, e2);
        float p3 = LOGIT(a3, b3, e3);
        #pragma unroll
        for (int o = 8; o > 0; o >>= 1) {
            p0 += __shfl_xor_sync(0xffffffffu, p0, o);
            p1 += __shfl_xor_sync(0xffffffffu, p1, o);
            p2 += __shfl_xor_sync(0xffffffffu, p2, o);
            p3 += __shfl_xor_sync(0xffffffffu, p3, o);
        }
        ONLINE_UPD(p0, a0, b0);
        ONLINE_UPD(p1, a1, b1);
        ONLINE_UPD(p2, a2, b2);
        ONLINE_UPD(p3, a3, b3);
    }
    for (; j < cnt; j++) {
        int2 ed0 = g_edge[beg + j];
        float e0 = __int_as_float(ed0.y);
        float4 a0 = xl4[ed0.x * 64 + idx0];
        float4 b0 = xl4[ed0.x * 64 + idx1];
        float p0 = LOGIT(a0, b0, e0);
        #pragma unroll
        for (int o = 8; o > 0; o >>= 1) p0 += __shfl_xor_sync(0xffffffffu, p0, o);
        ONLINE_UPD(p0, a0, b0);
    }
    #undef LOGIT
    #undef ONLINE_UPD

    float inv = 1.f / (s + 1e-16f);

    const float4* b4 = (const float4*)bias0;
    const float4* h4 = (const float4*)g_hidden;
    float4 bia = b4[idx0], bib = b4[idx1];
    float4 ha = h4[r * 64 + idx0], hb = h4[r * 64 + idx1];

    float4 v0, v1;
    v0.x = accA.x * inv + bia.x + ha.x; v0.y = accA.y * inv + bia.y + ha.y;
    v0.z = accA.z * inv + bia.z + ha.z; v0.w = accA.w * inv + bia.w + ha.w;
    v1.x = accB.x * inv + bib.x + hb.x; v1.y = accB.y * inv + bib.y + hb.y;
    v1.z = accB.z * inv + bib.z + hb.z; v1.w = accB.w * inv + bib.w + hb.w;

    float su = v0.x + v0.y + v0.z + v0.w + v1.x + v1.y + v1.z + v1.w;
    float sq = v0.x * v0.x + v0.y * v0.y + v0.z * v0.z + v0.w * v0.w
             + v1.x * v1.x + v1.y * v1.y + v1.z * v1.z + v1.w * v1.w;
    su = warp_sum(su);
    sq = warp_sum(sq);
    float mu = su / 256.f;
    float var = sq / 256.f - mu * mu;
    float rs = rsqrtf(var + 1e-5f);

    const float4* gg4 = (const float4*)g0;
    const float4* bb4 = (const float4*)be0;
    float4 ga = gg4[idx0], gb = gg4[idx1];
    float4 ba = bb4[idx0], bb = bb4[idx1];
    float4* out4 = (float4*)g_h1;
    float4 o0, o1;
    o0.x = fmaxf(0.f, (v0.x - mu) * rs * ga.x + ba.x);
    o0.y = fmaxf(0.f, (v0.y - mu) * rs * ga.y + ba.y);
    o0.z = fmaxf(0.f, (v0.z - mu) * rs * ga.z + ba.z);
    o0.w = fmaxf(0.f, (v0.w - mu) * rs * ga.w + ba.w);
    o1.x = fmaxf(0.f, (v1.x - mu) * rs * gb.x + bb.x);
    o1.y = fmaxf(0.f, (v1.y - mu) * rs * gb.y + bb.y);
    o1.z = fmaxf(0.f, (v1.z - mu) * rs * gb.z + bb.z);
    o1.w = fmaxf(0.f, (v1.w - mu) * rs * gb.w + bb.w);
    out4[r * 64 + idx0] = o0;
    out4[r * 64 + idx1] = o1;
}

// ---------------- fused layer-1: online-softmax GAT, 4-edge unroll ----------------
__global__ void k_node1(const float* __restrict__ We, const float* __restrict__ att,
                        const float* __restrict__ bias1, const float* __restrict__ g1,
                        const float* __restrict__ be1, float* __restrict__ out) {
    int r = blockIdx.x * (blockDim.x >> 5) + (threadIdx.x >> 5);
    if (r >= N_NODES) return;
    int lane = threadIdx.x & 31;

    float xr = g_xr1[r * DOUT + lane];
    float we = We[lane];
    float at = att[lane];

    const float NINF = __int_as_float(0xFF800000);
    float m = NINF, s = 0.f, acc = 0.f;

    const int beg = g_off[r], end = g_off[r + 1];
    const int cnt = end - beg;

    #define UPD1(p, x)                                                     \
        do {                                                               \
            if ((p) > m) { float c_ = __expf(m - (p)); s *= c_; acc *= c_; m = (p); } \
            float w_ = __expf((p) - m); s += w_; acc += w_ * (x);          \
        } while (0)

    int j = 0;
    for (; j + 3 < cnt; j += 4) {
        int2 ed0 = g_edge[beg + j],     ed1 = g_edge[beg + j + 1];
        int2 ed2 = g_edge[beg + j + 2], ed3 = g_edge[beg + j + 3];
        float e0 = __int_as_float(ed0.y), e1 = __int_as_float(ed1.y);
        float e2 = __int_as_float(ed2.y), e3 = __int_as_float(ed3.y);
        float x0 = g_xl1[ed0.x * DOUT + lane];
        float x1 = g_xl1[ed1.x * DOUT + lane];
        float x2 = g_xl1[ed2.x * DOUT + lane];
        float x3 = g_xl1[ed3.x * DOUT + lane];

        float p0 = lrelu(x0 + xr + e0 * we) * at;
        float p1 = lrelu(x1 + xr + e1 * we) * at;
        float p2 = lrelu(x2 + xr + e2 * we) * at;
        float p3 = lrelu(x3 + xr + e3 * we) * at;
        #pragma unroll
        for (int o = 8; o > 0; o >>= 1) {
            p0 += __shfl_xor_sync(0xffffffffu, p0, o);
            p1 += __shfl_xor_sync(0xffffffffu, p1, o);
            p2 += __shfl_xor_sync(0xffffffffu, p2, o);
            p3 += __shfl_xor_sync(0xffffffffu, p3, o);
        }
        UPD1(p0, x0);
        UPD1(p1, x1);
        UPD1(p2, x2);
        UPD1(p3, x3);
    }
    for (; j < cnt; j++) {
        int2 ed0 = g_edge[beg + j];
        float e0 = __int_as_float(ed0.y);
        float x0 = g_xl1[ed0.x * DOUT + lane];
        float p0 = lrelu(x0 + xr + e0 * we) * at;
        #pragma unroll
        for (int o = 8; o > 0; o >>= 1) p0 += __shfl_xor_sync(0xffffffffu, p0, o);
        UPD1(p0, x0);
    }
    #undef UPD1

    float t = acc / (s + 1e-16f) + bias1[lane];
    float su = warp_sum(t);
    float sq = warp_sum(t * t);
    float mu = su / 32.f;
    float var = sq / 32.f - mu * mu;
    float rs = rsqrtf(var + 1e-5f);
    out[r * DOUT + lane] = fmaxf(0.f, (t - mu) * rs * g1[lane] + be1[lane]);
}

// ---------------- launch ----------------
extern "C" void kernel_launch(void* const* d_in, const int* in_sizes, int n_in,
                              void* d_out, int out_size) {
    const float* x     = (const float*)d_in[0];
    const int*   ei    = (const int*)d_in[1];
    const float* eattr = (const float*)d_in[2];
    const float* Wp    = (const float*)d_in[3];
    const float* bp    = (const float*)d_in[4];
    const float* Wl0   = (const float*)d_in[5];
    const float* bl0   = (const float*)d_in[6];
    const float* Wr0   = (const float*)d_in[7];
    const float* br0   = (const float*)d_in[8];
    const float* We0   = (const float*)d_in[9];
    const float* att0  = (const float*)d_in[10];
    const float* bias0 = (const float*)d_in[11];
    const float* g0    = (const float*)d_in[12];
    const float* be0   = (const float*)d_in[13];
    const float* Wl1   = (const float*)d_in[14];
    const float* bl1   = (const float*)d_in[15];
    const float* Wr1   = (const float*)d_in[16];
    const float* br1   = (const float*)d_in[17];
    const float* We1   = (const float*)d_in[18];
    const float* att1  = (const float*)d_in[19];
    const float* bias1 = (const float*)d_in[20];
    const float* g1    = (const float*)d_in[21];
    const float* be1   = (const float*)d_in[22];
    float* out = (float*)d_out;

    float *hidden, *xl0, *xr0, *h1, *xl1, *xr1, *wcat0, *wcat1, *bcat0, *bcat1;
    cudaGetSymbolAddress((void**)&hidden, g_hidden);
    cudaGetSymbolAddress((void**)&xl0, g_xl0);
    cudaGetSymbolAddress((void**)&xr0, g_xr0);
    cudaGetSymbolAddress((void**)&h1, g_h1);
    cudaGetSymbolAddress((void**)&xl1, g_xl1);
    cudaGetSymbolAddress((void**)&xr1, g_xr1);
    cudaGetSymbolAddress((void**)&wcat0, g_wcat0);
    cudaGetSymbolAddress((void**)&wcat1, g_wcat1);
    cudaGetSymbolAddress((void**)&bcat0, g_bcat0);
    cudaGetSymbolAddress((void**)&bcat1, g_bcat1);

    // ---- fork: CSR branch on g_sh.s, prep on g_sh.s2, GEMMs on stream 0 ----
    cudaEventRecord(g_sh.ef, 0);
    cudaStreamWaitEvent(g_sh.s, g_sh.ef, 0);
    cudaStreamWaitEvent(g_sh.s2, g_sh.ef, 0);

    // CSR branch
    k_init_ea<<<64, 256, 0, g_sh.s>>>(eattr);
    k_hist<<<(E_EDGES + 255) / 256, 256, 0, g_sh.s>>>(ei);
    k_scan<<<1, 1024, 0, g_sh.s>>>();
    k_selfloop<<<(N_NODES + 255) / 256, 256, 0, g_sh.s>>>();
    k_scatter<<<(E_EDGES + 255) / 256, 256, 0, g_sh.s>>>(ei, eattr);
    cudaEventRecord(g_sh.ej, g_sh.s);

    // prep branch (weights concat — only needed by gemm_cat)
    k_prep<<<256, 256, 0, g_sh.s2>>>(Wl0, Wr0, bl0, br0, Wl1, Wr1, bl1, br1);
    cudaEventRecord(g_sh.ep, g_sh.s2);

    // GEMM branch (stream 0)
    {
        dim3 grid(256 / 64, (N_NODES + 127) / 128);
        mma_gemm<false><<<grid, 256>>>(x, Wp, bp, hidden, nullptr, N_NODES, 256, 512);
    }
    cudaStreamWaitEvent(0, g_sh.ep, 0);   // wcat0/bcat0 ready
    {
        dim3 grid(512 / 64, (N_NODES + 127) / 128);
        mma_gemm<true><<<grid, 256>>>(hidden, wcat0, bcat0, xl0, xr0, N_NODES, 512, HID);
    }

    // ---- join: k_node0 needs CSR + xl0/xr0 ----
    cudaStreamWaitEvent(0, g_sh.ej, 0);

    k_node0<<<(N_NODES + 7) / 8, 256>>>(We0, att0, bias0, g0, be0);

    {
        dim3 grid(64 / 64, (N_NODES + 127) / 128);
        mma_gemm<true><<<grid, 256>>>(h1, wcat1, bcat1, xl1, xr1, N_NODES, 64, HID);
    }

    k_node1<<<(N_NODES + 7) / 8, 256>>>(We1, att1, bias1, g1, be1, out);
}

// round 13
// speedup vs baseline: 1.0816x; 1.0816x over previous
#include <cuda_runtime.h>
#include <math.h>
#include <stdint.h>

#define N_NODES 10000
#define E_EDGES 320000
#define E_TOT   330000   // + self loops
#define HID     256
#define DOUT    32

// ---------------- scratch (device globals) ----------------
__device__ float g_hidden[N_NODES * HID];
__device__ float g_xl0[N_NODES * HID];
__device__ float g_xr0[N_NODES * HID];
__device__ float g_h1[N_NODES * HID];
__device__ float g_xl1[N_NODES * DOUT];
__device__ float g_xr1[N_NODES * DOUT];
__device__ float g_wcat0[HID * (2 * HID)];   // [256 x 512]
__device__ float g_wcat1[HID * (2 * DOUT)];  // [256 x 64]
__device__ float g_bcat0[2 * HID];
__device__ float g_bcat1[2 * DOUT];
__device__ int   g_count[N_NODES];
__device__ int   g_off[N_NODES + 1];
__device__ int   g_rank[E_EDGES];
__device__ int2  g_edge[E_TOT];              // packed (src, ea-bits)
__device__ float g_ea_part[64];
__device__ float g_ea_mean;

// ---------------- streams/events for fork-join (created at load) ----------------
struct StreamHolder {
    cudaStream_t s, s2;
    cudaEvent_t ef, ej, ep;
    StreamHolder() {
        cudaStreamCreateWithFlags(&s, cudaStreamNonBlocking);
        cudaStreamCreateWithFlags(&s2, cudaStreamNonBlocking);
        cudaEventCreateWithFlags(&ef, cudaEventDisableTiming);
        cudaEventCreateWithFlags(&ej, cudaEventDisableTiming);
        cudaEventCreateWithFlags(&ep, cudaEventDisableTiming);
    }
};
static StreamHolder g_sh;

// ---------------- helpers ----------------
__device__ __forceinline__ float lrelu(float v) { return v > 0.f ? v : 0.2f * v; }

__device__ __forceinline__ float warp_sum(float v) {
    #pragma unroll
    for (int o = 16; o > 0; o >>= 1) v += __shfl_xor_sync(0xffffffffu, v, o);
    return v;
}

__device__ __forceinline__ uint32_t f2tf32(float x) {
    uint32_t r;
    asm("cvt.rna.tf32.f32 %0, %1;" : "=r"(r) : "f"(x));
    return r;
}

__device__ __forceinline__ void mma_tf32(float* c, const uint32_t* a, uint32_t b0, uint32_t b1) {
    asm volatile(
        "mma.sync.aligned.m16n8k8.row.col.f32.tf32.tf32.f32 "
        "{%0,%1,%2,%3},{%4,%5,%6,%7},{%8,%9},{%0,%1,%2,%3};"
        : "+f"(c[0]), "+f"(c[1]), "+f"(c[2]), "+f"(c[3])
        : "r"(a[0]), "r"(a[1]), "r"(a[2]), "r"(a[3]), "r"(b0), "r"(b1));
}

// ---------------- prep: concat weights/biases ----------------
__global__ void k_prep(const float* __restrict__ Wl0, const float* __restrict__ Wr0,
                       const float* __restrict__ bl0, const float* __restrict__ br0,
                       const float* __restrict__ Wl1, const float* __restrict__ Wr1,
                       const float* __restrict__ bl1, const float* __restrict__ br1) {
    int i = blockIdx.x * blockDim.x + threadIdx.x;
    int stride = gridDim.x * blockDim.x;
    for (int idx = i; idx < HID * 2 * HID; idx += stride) {
        int r = idx >> 9, c = idx & 511;
        g_wcat0[idx] = (c < HID) ? Wl0[r * HID + c] : Wr0[r * HID + c - HID];
    }
    for (int idx = i; idx < HID * 2 * DOUT; idx += stride) {
        int r = idx >> 6, c = idx & 63;
        g_wcat1[idx] = (c < DOUT) ? Wl1[r * DOUT + c] : Wr1[r * DOUT + c - DOUT];
    }
    if (i < 2 * HID) g_bcat0[i] = (i < HID) ? bl0[i] : br0[i - HID];
    if (i < 2 * DOUT) g_bcat1[i] = (i < DOUT) ? bl1[i] : br1[i - DOUT];
}

// ---------------- CSR branch: init counts + per-block edge_attr partial sums ----------------
__global__ void k_init_ea(const float* __restrict__ ea) {
    __shared__ float sh[8];
    int i = blockIdx.x * blockDim.x + threadIdx.x;
    int stride = gridDim.x * blockDim.x;
    for (int j = i; j < N_NODES; j += stride) g_count[j] = 1;
    float s = 0.f;
    for (int j = i; j < E_EDGES; j += stride) s += ea[j];
    s = warp_sum(s);
    int lane = threadIdx.x & 31, wid = threadIdx.x >> 5;
    if (lane == 0) sh[wid] = s;
    __syncthreads();
    if (wid == 0) {
        s = (lane < (blockDim.x >> 5)) ? sh[lane] : 0.f;
        s = warp_sum(s);
        if (lane == 0) g_ea_part[blockIdx.x] = s;
    }
}

// ---------------- histogram by dst; atomic return value IS the edge's slot rank ----------------
__global__ void k_hist(const int* __restrict__ ei) {
    int e = blockIdx.x * blockDim.x + threadIdx.x;
    if (e < E_EDGES) {
        int rank = atomicAdd(&g_count[ei[E_EDGES + e]], 1);  // >=1 (slot 0 = self loop)
        g_rank[e] = rank;
    }
}

// ---------------- 1-block scan of offsets + ea-mean reduce ----------------
__global__ void k_scan() {
    __shared__ int warp_tot[32];
    const int t = threadIdx.x;
    const int lane = t & 31, wid = t >> 5;
    const int CH = 10;
    int base = t * CH;
    int local[CH];
    int s = 0;
    #pragma unroll
    for (int i = 0; i < CH; i++) {
        int idx = base + i;
        int v = (idx < N_NODES) ? g_count[idx] : 0;
        local[i] = s;
        s += v;
    }
    int x = s;
    #pragma unroll
    for (int o = 1; o < 32; o <<= 1) {
        int y = __shfl_up_sync(0xffffffffu, x, o);
        if (lane >= o) x += y;
    }
    if (lane == 31) warp_tot[wid] = x;
    __syncthreads();
    if (wid == 0) {
        int w = warp_tot[lane];
        #pragma unroll
        for (int o = 1; o < 32; o <<= 1) {
            int y = __shfl_up_sync(0xffffffffu, w, o);
            if (lane >= o) w += y;
        }
        warp_tot[lane] = w;
    }
    if (wid == 1) {
        float v = g_ea_part[lane] + g_ea_part[lane + 32];
        v = warp_sum(v);
        if (lane == 0) g_ea_mean = v * (1.f / (float)E_EDGES);
    }
    __syncthreads();
    int pre = x - s + (wid > 0 ? warp_tot[wid - 1] : 0);
    #pragma unroll
    for (int i = 0; i < CH; i++) {
        int idx = base + i;
        if (idx <= N_NODES) g_off[idx] = pre + local[i];
    }
}

// ---------------- scatter edges + self loops (no cursor atomics) ----------------
__global__ void k_scatter(const int* __restrict__ ei, const float* __restrict__ eattr) {
    int e = blockIdx.x * blockDim.x + threadIdx.x;
    if (e < E_EDGES) {
        int dst = ei[E_EDGES + e];
        int pos = g_off[dst] + g_rank[e];
        g_edge[pos] = make_int2(ei[e], __float_as_int(eattr[e]));
    } else if (e < E_TOT) {
        int i = e - E_EDGES;
        g_edge[g_off[i]] = make_int2(i, __float_as_int(g_ea_mean));
    }
}

// ---------------- tf32 tensor-core GEMM: C = A[M,K] @ B[K,Nc] + bias ----------------
template<bool SPLIT>
__global__ void mma_gemm(const float* __restrict__ A, const float* __restrict__ B,
                         const float* __restrict__ bias,
                         float* __restrict__ C0, float* __restrict__ C1,
                         int M, int Nc, int K) {
    constexpr int BM = 128, BN = 64, BK = 32;
    constexpr int NT = 256;
    constexpr int NA = BM * BK / 4 / NT;
    constexpr int NB = BK * BN / 4 / NT;
    __shared__ uint32_t As[BM][BK + 4];
    __shared__ uint32_t Bs[BK][BN + 4];

    const int tid = threadIdx.x;
    const int wid = tid >> 5;
    const int lane = tid & 31;
    const int gid = lane >> 2;
    const int tg  = lane & 3;
    const int wm = (wid & 3) * 32;
    const int wn = (wid >> 2) * 32;
    const int row0 = blockIdx.y * BM, col0 = blockIdx.x * BN;

    float acc[2][4][4];
    #pragma unroll
    for (int mt = 0; mt < 2; mt++)
        #pragma unroll
        for (int nt = 0; nt < 4; nt++)
            #pragma unroll
            for (int i = 0; i < 4; i++) acc[mt][nt][i] = 0.f;

    float4 ra[NA], rb[NB];

    auto g2r = [&](int k0) {
        #pragma unroll
        for (int i = 0; i < NA; i++) {
            int lin = (tid + i * NT) * 4;
            int r = lin / BK, c = lin % BK;
            int gr = row0 + r;
            ra[i] = (gr < M) ? *(const float4*)&A[(size_t)gr * K + k0 + c]
                             : make_float4(0.f, 0.f, 0.f, 0.f);
        }
        #pragma unroll
        for (int i = 0; i < NB; i++) {
            int lin = (tid + i * NT) * 4;
            int kr = lin / BN, c = lin % BN;
            rb[i] = *(const float4*)&B[(size_t)(k0 + kr) * Nc + col0 + c];
        }
    };
    auto r2s = [&]() {
        #pragma unroll
        for (int i = 0; i < NA; i++) {
            int lin = (tid + i * NT) * 4;
            int r = lin / BK, c = lin % BK;
            As[r][c + 0] = f2tf32(ra[i].x); As[r][c + 1] = f2tf32(ra[i].y);
            As[r][c + 2] = f2tf32(ra[i].z); As[r][c + 3] = f2tf32(ra[i].w);
        }
        #pragma unroll
        for (int i = 0; i < NB; i++) {
            int lin = (tid + i * NT) * 4;
            int kr = lin / BN, c = lin % BN;
            Bs[kr][c + 0] = f2tf32(rb[i].x); Bs[kr][c + 1] = f2tf32(rb[i].y);
            Bs[kr][c + 2] = f2tf32(rb[i].z); Bs[kr][c + 3] = f2tf32(rb[i].w);
        }
    };

    g2r(0);
    r2s();
    __syncthreads();

    const int NTILES = K / BK;
    for (int t = 0; t < NTILES; t++) {
        if (t + 1 < NTILES) g2r((t + 1) * BK);
        #pragma unroll
        for (int ks = 0; ks < BK; ks += 8) {
            uint32_t af[2][4];
            #pragma unroll
            for (int mt = 0; mt < 2; mt++) {
                int r0 = wm + mt * 16 + gid;
                af[mt][0] = As[r0][ks + tg];
                af[mt][1] = As[r0 + 8][ks + tg];
                af[mt][2] = As[r0][ks + tg + 4];
                af[mt][3] = As[r0 + 8][ks + tg + 4];
            }
            #pragma unroll
            for (int nt = 0; nt < 4; nt++) {
                int cn = wn + nt * 8 + gid;
                uint32_t b0 = Bs[ks + tg][cn];
                uint32_t b1 = Bs[ks + tg + 4][cn];
                #pragma unroll
                for (int mt = 0; mt < 2; mt++)
                    mma_tf32(acc[mt][nt], af[mt], b0, b1);
            }
        }
        if (t + 1 < NTILES) {
            __syncthreads();
            r2s();
            __syncthreads();
        }
    }

    const int S = Nc >> 1;
    #pragma unroll
    for (int mt = 0; mt < 2; mt++) {
        int gr0 = row0 + wm + mt * 16 + gid;
        int gr1 = gr0 + 8;
        #pragma unroll
        for (int nt = 0; nt < 4; nt++) {
            int gc = col0 + wn + nt * 8 + tg * 2;
            float b0 = bias[gc], b1 = bias[gc + 1];
            float v00 = acc[mt][nt][0] + b0, v01 = acc[mt][nt][1] + b1;
            float v10 = acc[mt][nt][2] + b0, v11 = acc[mt][nt][3] + b1;
            if (SPLIT) {
                if (gr0 < M) {
                    if (gc < S) { C0[(size_t)gr0 * S + gc] = v00; } else { C1[(size_t)gr0 * S + gc - S] = v00; }
                    if (gc + 1 < S) { C0[(size_t)gr0 * S + gc + 1] = v01; } else { C1[(size_t)gr0 * S + gc + 1 - S] = v01; }
                }
                if (gr1 < M) {
                    if (gc < S) { C0[(size_t)gr1 * S + gc] = v10; } else { C1[(size_t)gr1 * S + gc - S] = v10; }
                    if (gc + 1 < S) { C0[(size_t)gr1 * S + gc + 1] = v11; } else { C1[(size_t)gr1 * S + gc + 1 - S] = v11; }
                }
            } else {
                if (gr0 < M) *(float2*)&C0[(size_t)gr0 * Nc + gc] = make_float2(v00, v01);
                if (gr1 < M) *(float2*)&C0[(size_t)gr1 * Nc + gc] = make_float2(v10, v11);
            }
        }
    }
}

// ---------------- fused layer-0: 2 warps per node, online softmax + smem merge ----------------
// block = 8 warps = 4 nodes. Warp pair (2w, 2w+1) splits node's edges at stride 2.
__global__ void k_node0(const float* __restrict__ We, const float* __restrict__ att,
                        const float* __restrict__ bias0, const float* __restrict__ g0,
                        const float* __restrict__ be0) {
    __shared__ float smerge[8][32][10];   // [warp][lane][accA4|accB4|m|s]

    const int warp = threadIdx.x >> 5;
    const int lane = threadIdx.x & 31;
    const int r = blockIdx.x * 4 + (warp >> 1);    // N_NODES % 4 == 0: always valid
    const int half = warp & 1;
    const int idx0 = lane * 2, idx1 = lane * 2 + 1;

    const float4* xl4 = (const float4*)g_xl0;
    const float4* xr4 = (const float4*)g_xr0;
    const float4* We4 = (const float4*)We;
    const float4* at4 = (const float4*)att;

    float4 xra = xr4[r * 64 + idx0], xrb = xr4[r * 64 + idx1];
    float4 wea = We4[idx0],          web = We4[idx1];
    float4 ata = at4[idx0],          atb = at4[idx1];

    const float NINF = __int_as_float(0xFF800000);
    float m = NINF, s = 0.f;
    float4 accA = make_float4(0.f, 0.f, 0.f, 0.f);
    float4 accB = make_float4(0.f, 0.f, 0.f, 0.f);

    const int beg = g_off[r], end = g_off[r + 1];

    #define LOGIT(a, b, ea)                                              \
        (lrelu((a).x + xra.x + (ea) * wea.x) * ata.x                     \
       + lrelu((a).y + xra.y + (ea) * wea.y) * ata.y                     \
       + lrelu((a).z + xra.z + (ea) * wea.z) * ata.z                     \
       + lrelu((a).w + xra.w + (ea) * wea.w) * ata.w                     \
       + lrelu((b).x + xrb.x + (ea) * web.x) * atb.x                     \
       + lrelu((b).y + xrb.y + (ea) * web.y) * atb.y                     \
       + lrelu((b).z + xrb.z + (ea) * web.z) * atb.z                     \
       + lrelu((b).w + xrb.w + (ea) * web.w) * atb.w)

    #define ONLINE_UPD(p, a, b)                                           \
        do {                                                              \
            if ((p) > m) {                                                \
                float c_ = __expf(m - (p));                               \
                s *= c_;                                                  \
                accA.x *= c_; accA.y *= c_; accA.z *= c_; accA.w *= c_;   \
                accB.x *= c_; accB.y *= c_; accB.z *= c_; accB.w *= c_;   \
                m = (p);                                                  \
            }                                                             \
            float w_ = __expf((p) - m);                                   \
            s += w_;                                                      \
            accA.x += w_ * (a).x; accA.y += w_ * (a).y;                   \
            accA.z += w_ * (a).z; accA.w += w_ * (a).w;                   \
            accB.x += w_ * (b).x; accB.y += w_ * (b).y;                   \
            accB.z += w_ * (b).z; accB.w += w_ * (b).w;                   \
        } while (0)

    int j = beg + half;
    for (; j + 2 < end; j += 4) {   // two edges: j and j+2
        int2 ed0 = g_edge[j], ed1 = g_edge[j + 2];
        float e0 = __int_as_float(ed0.y), e1 = __int_as_float(ed1.y);
        float4 a0 = xl4[ed0.x * 64 + idx0];
        float4 b0 = xl4[ed0.x * 64 + idx1];
        float4 a1 = xl4[ed1.x * 64 + idx0];
        float4 b1 = xl4[ed1.x * 64 + idx1];

        float p0 = LOGIT(a0, b0, e0);
        float p1 = LOGIT(a1, b1, e1);
        #pragma unroll
        for (int o = 8; o > 0; o >>= 1) {
            p0 += __shfl_xor_sync(0xffffffffu, p0, o);
            p1 += __shfl_xor_sync(0xffffffffu, p1, o);
        }
        ONLINE_UPD(p0, a0, b0);
        ONLINE_UPD(p1, a1, b1);
    }
    if (j < end) {
        int2 ed0 = g_edge[j];
        float e0 = __int_as_float(ed0.y);
        float4 a0 = xl4[ed0.x * 64 + idx0];
        float4 b0 = xl4[ed0.x * 64 + idx1];
        float p0 = LOGIT(a0, b0, e0);
        #pragma unroll
        for (int o = 8; o > 0; o >>= 1) p0 += __shfl_xor_sync(0xffffffffu, p0, o);
        ONLINE_UPD(p0, a0, b0);
    }
    #undef LOGIT
    #undef ONLINE_UPD

    // publish partial state
    float* st = smerge[warp][lane];
    st[0] = accA.x; st[1] = accA.y; st[2] = accA.z; st[3] = accA.w;
    st[4] = accB.x; st[5] = accB.y; st[6] = accB.z; st[7] = accB.w;
    st[8] = m; st[9] = s;
    __syncthreads();
    if (half) return;   // odd warps done (after the sync)

    // merge partner state (same head per lane)
    {
        const float* pt = smerge[warp + 1][lane];
        float mB = pt[8], sB = pt[9];
        float M = fmaxf(m, mB);
        float cA = __expf(m - M), cB = __expf(mB - M);
        s = s * cA + sB * cB;
        accA.x = accA.x * cA + pt[0] * cB; accA.y = accA.y * cA + pt[1] * cB;
        accA.z = accA.z * cA + pt[2] * cB; accA.w = accA.w * cA + pt[3] * cB;
        accB.x = accB.x * cA + pt[4] * cB; accB.y = accB.y * cA + pt[5] * cB;
        accB.z = accB.z * cA + pt[6] * cB; accB.w = accB.w * cA + pt[7] * cB;
    }

    float inv = 1.f / (s + 1e-16f);

    const float4* b4 = (const float4*)bias0;
    const float4* h4 = (const float4*)g_hidden;
    float4 bia = b4[idx0], bib = b4[idx1];
    float4 ha = h4[r * 64 + idx0], hb = h4[r * 64 + idx1];

    float4 v0, v1;
    v0.x = accA.x * inv + bia.x + ha.x; v0.y = accA.y * inv + bia.y + ha.y;
    v0.z = accA.z * inv + bia.z + ha.z; v0.w = accA.w * inv + bia.w + ha.w;
    v1.x = accB.x * inv + bib.x + hb.x; v1.y = accB.y * inv + bib.y + hb.y;
    v1.z = accB.z * inv + bib.z + hb.z; v1.w = accB.w * inv + bib.w + hb.w;

    float su = v0.x + v0.y + v0.z + v0.w + v1.x + v1.y + v1.z + v1.w;
    float sq = v0.x * v0.x + v0.y * v0.y + v0.z * v0.z + v0.w * v0.w
             + v1.x * v1.x + v1.y * v1.y + v1.z * v1.z + v1.w * v1.w;
    su = warp_sum(su);
    sq = warp_sum(sq);
    float mu = su / 256.f;
    float var = sq / 256.f - mu * mu;
    float rs = rsqrtf(var + 1e-5f);

    const float4* gg4 = (const float4*)g0;
    const float4* bb4 = (const float4*)be0;
    float4 ga = gg4[idx0], gb = gg4[idx1];
    float4 ba = bb4[idx0], bb = bb4[idx1];
    float4* out4 = (float4*)g_h1;
    float4 o0, o1;
    o0.x = fmaxf(0.f, (v0.x - mu) * rs * ga.x + ba.x);
    o0.y = fmaxf(0.f, (v0.y - mu) * rs * ga.y + ba.y);
    o0.z = fmaxf(0.f, (v0.z - mu) * rs * ga.z + ba.z);
    o0.w = fmaxf(0.f, (v0.w - mu) * rs * ga.w + ba.w);
    o1.x = fmaxf(0.f, (v1.x - mu) * rs * gb.x + bb.x);
    o1.y = fmaxf(0.f, (v1.y - mu) * rs * gb.y + bb.y);
    o1.z = fmaxf(0.f, (v1.z - mu) * rs * gb.z + bb.z);
    o1.w = fmaxf(0.f, (v1.w - mu) * rs * gb.w + bb.w);
    out4[r * 64 + idx0] = o0;
    out4[r * 64 + idx1] = o1;
}

// ---------------- fused layer-1: 2 warps per node, online softmax + smem merge ----------------
__global__ void k_node1(const float* __restrict__ We, const float* __restrict__ att,
                        const float* __restrict__ bias1, const float* __restrict__ g1,
                        const float* __restrict__ be1, float* __restrict__ out) {
    __shared__ float smerge[8][32][3];   // [warp][lane][acc|m|s]

    const int warp = threadIdx.x >> 5;
    const int lane = threadIdx.x & 31;
    const int r = blockIdx.x * 4 + (warp >> 1);
    const int half = warp & 1;

    float xr = g_xr1[r * DOUT + lane];
    float we = We[lane];
    float at = att[lane];

    const float NINF = __int_as_float(0xFF800000);
    float m = NINF, s = 0.f, acc = 0.f;

    const int beg = g_off[r], end = g_off[r + 1];

    #define UPD1(p, x)                                                     \
        do {                                                               \
            if ((p) > m) { float c_ = __expf(m - (p)); s *= c_; acc *= c_; m = (p); } \
            float w_ = __expf((p) - m); s += w_; acc += w_ * (x);          \
        } while (0)

    int j = beg + half;
    for (; j + 2 < end; j += 4) {
        int2 ed0 = g_edge[j], ed1 = g_edge[j + 2];
        float e0 = __int_as_float(ed0.y), e1 = __int_as_float(ed1.y);
        float x0 = g_xl1[ed0.x * DOUT + lane];
        float x1 = g_xl1[ed1.x * DOUT + lane];

        float p0 = lrelu(x0 + xr + e0 * we) * at;
        float p1 = lrelu(x1 + xr + e1 * we) * at;
        #pragma unroll
        for (int o = 8; o > 0; o >>= 1) {
            p0 += __shfl_xor_sync(0xffffffffu, p0, o);
            p1 += __shfl_xor_sync(0xffffffffu, p1, o);
        }
        UPD1(p0, x0);
        UPD1(p1, x1);
    }
    if (j < end) {
        int2 ed0 = g_edge[j];
        float e0 = __int_as_float(ed0.y);
        float x0 = g_xl1[ed0.x * DOUT + lane];
        float p0 = lrelu(x0 + xr + e0 * we) * at;
        #pragma unroll
        for (int o = 8; o > 0; o >>= 1) p0 += __shfl_xor_sync(0xffffffffu, p0, o);
        UPD1(p0, x0);
    }
    #undef UPD1

    float* st = smerge[warp][lane];
    st[0] = acc; st[1] = m; st[2] = s;
    __syncthreads();
    if (half) return;

    {
        const float* pt = smerge[warp + 1][lane];
        float mB = pt[1], sB = pt[2];
        float M = fmaxf(m, mB);
        float cA = __expf(m - M), cB = __expf(mB - M);
        s = s * cA + sB * cB;
        acc = acc * cA + pt[0] * cB;
    }

    float t = acc / (s + 1e-16f) + bias1[lane];
    float su = warp_sum(t);
    float sq = warp_sum(t * t);
    float mu = su / 32.f;
    float var = sq / 32.f - mu * mu;
    float rs = rsqrtf(var + 1e-5f);
    out[r * DOUT + lane] = fmaxf(0.f, (t - mu) * rs * g1[lane] + be1[lane]);
}

// ---------------- launch ----------------
extern "C" void kernel_launch(void* const* d_in, const int* in_sizes, int n_in,
                              void* d_out, int out_size) {
    const float* x     = (const float*)d_in[0];
    const int*   ei    = (const int*)d_in[1];
    const float* eattr = (const float*)d_in[2];
    const float* Wp    = (const float*)d_in[3];
    const float* bp    = (const float*)d_in[4];
    const float* Wl0   = (const float*)d_in[5];
    const float* bl0   = (const float*)d_in[6];
    const float* Wr0   = (const float*)d_in[7];
    const float* br0   = (const float*)d_in[8];
    const float* We0   = (const float*)d_in[9];
    const float* att0  = (const float*)d_in[10];
    const float* bias0 = (const float*)d_in[11];
    const float* g0    = (const float*)d_in[12];
    const float* be0   = (const float*)d_in[13];
    const float* Wl1   = (const float*)d_in[14];
    const float* bl1   = (const float*)d_in[15];
    const float* Wr1   = (const float*)d_in[16];
    const float* br1   = (const float*)d_in[17];
    const float* We1   = (const float*)d_in[18];
    const float* att1  = (const float*)d_in[19];
    const float* bias1 = (const float*)d_in[20];
    const float* g1    = (const float*)d_in[21];
    const float* be1   = (const float*)d_in[22];
    float* out = (float*)d_out;

    float *hidden, *xl0, *xr0, *h1, *xl1, *xr1, *wcat0, *wcat1, *bcat0, *bcat1;
    cudaGetSymbolAddress((void**)&hidden, g_hidden);
    cudaGetSymbolAddress((void**)&xl0, g_xl0);
    cudaGetSymbolAddress((void**)&xr0, g_xr0);
    cudaGetSymbolAddress((void**)&h1, g_h1);
    cudaGetSymbolAddress((void**)&xl1, g_xl1);
    cudaGetSymbolAddress((void**)&xr1, g_xr1);
    cudaGetSymbolAddress((void**)&wcat0, g_wcat0);
    cudaGetSymbolAddress((void**)&wcat1, g_wcat1);
    cudaGetSymbolAddress((void**)&bcat0, g_bcat0);
    cudaGetSymbolAddress((void**)&bcat1, g_bcat1);

    // ---- fork: CSR branch on g_sh.s, prep on g_sh.s2, GEMMs on stream 0 ----
    cudaEventRecord(g_sh.ef, 0);
    cudaStreamWaitEvent(g_sh.s, g_sh.ef, 0);
    cudaStreamWaitEvent(g_sh.s2, g_sh.ef, 0);

    // CSR branch (4 kernels)
    k_init_ea<<<64, 256, 0, g_sh.s>>>(eattr);
    k_hist<<<(E_EDGES + 255) / 256, 256, 0, g_sh.s>>>(ei);
    k_scan<<<1, 1024, 0, g_sh.s>>>();
    k_scatter<<<(E_TOT + 255) / 256, 256, 0, g_sh.s>>>(ei, eattr);
    cudaEventRecord(g_sh.ej, g_sh.s);

    // prep branch
    k_prep<<<256, 256, 0, g_sh.s2>>>(Wl0, Wr0, bl0, br0, Wl1, Wr1, bl1, br1);
    cudaEventRecord(g_sh.ep, g_sh.s2);

    // GEMM branch (stream 0)
    {
        dim3 grid(256 / 64, (N_NODES + 127) / 128);
        mma_gemm<false><<<grid, 256>>>(x, Wp, bp, hidden, nullptr, N_NODES, 256, 512);
    }
    cudaStreamWaitEvent(0, g_sh.ep, 0);
    {
        dim3 grid(512 / 64, (N_NODES + 127) / 128);
        mma_gemm<true><<<grid, 256>>>(hidden, wcat0, bcat0, xl0, xr0, N_NODES, 512, HID);
    }

    // ---- join: k_node0 needs CSR + xl0/xr0 ----
    cudaStreamWaitEvent(0, g_sh.ej, 0);

    k_node0<<<N_NODES / 4, 256>>>(We0, att0, bias0, g0, be0);

    {
        dim3 grid(64 / 64, (N_NODES + 127) / 128);
        mma_gemm<true><<<grid, 256>>>(h1, wcat1, bcat1, xl1, xr1, N_NODES, 64, HID);
    }

    k_node1<<<N_NODES / 4, 256>>>(We1, att1, bias1, g1, be1, out);
}

// round 14
// speedup vs baseline: 1.1330x; 1.0476x over previous
#include <cuda_runtime.h>
#include <cuda_fp16.h>
#include <math.h>
#include <stdint.h>

#define N_NODES 10000
#define E_EDGES 320000
#define E_TOT   330000   // + self loops
#define HID     256
#define DOUT    32

// ---------------- scratch (device globals) ----------------
__device__ float  g_hidden[N_NODES * HID];
__device__ __half g_xl0h[N_NODES * HID];     // fp16 gather table for layer-0
__device__ float  g_xr0[N_NODES * HID];
__device__ float  g_h1[N_NODES * HID];
__device__ float  g_xl1[N_NODES * DOUT];
__device__ float  g_xr1[N_NODES * DOUT];
__device__ float  g_wcat0[HID * (2 * HID)];  // [256 x 512]
__device__ float  g_wcat1[HID * (2 * DOUT)]; // [256 x 64]
__device__ float  g_bcat0[2 * HID];
__device__ float  g_bcat1[2 * DOUT];
__device__ int    g_count[N_NODES];
__device__ int    g_off[N_NODES + 1];
__device__ int    g_rank[E_EDGES];
__device__ int2   g_edge[E_TOT];             // packed (src, ea-bits)
__device__ float  g_ea_part[64];
__device__ float  g_ea_mean;

// ---------------- streams/events for fork-join (created at load) ----------------
struct StreamHolder {
    cudaStream_t s, s2;
    cudaEvent_t ef, ej, ep;
    StreamHolder() {
        cudaStreamCreateWithFlags(&s, cudaStreamNonBlocking);
        cudaStreamCreateWithFlags(&s2, cudaStreamNonBlocking);
        cudaEventCreateWithFlags(&ef, cudaEventDisableTiming);
        cudaEventCreateWithFlags(&ej, cudaEventDisableTiming);
        cudaEventCreateWithFlags(&ep, cudaEventDisableTiming);
    }
};
static StreamHolder g_sh;

// ---------------- helpers ----------------
__device__ __forceinline__ float lrelu(float v) { return v > 0.f ? v : 0.2f * v; }

__device__ __forceinline__ float warp_sum(float v) {
    #pragma unroll
    for (int o = 16; o > 0; o >>= 1) v += __shfl_xor_sync(0xffffffffu, v, o);
    return v;
}

__device__ __forceinline__ uint32_t f2tf32(float x) {
    uint32_t r;
    asm("cvt.rna.tf32.f32 %0, %1;" : "=r"(r) : "f"(x));
    return r;
}

__device__ __forceinline__ void mma_tf32(float* c, const uint32_t* a, uint32_t b0, uint32_t b1) {
    asm volatile(
        "mma.sync.aligned.m16n8k8.row.col.f32.tf32.tf32.f32 "
        "{%0,%1,%2,%3},{%4,%5,%6,%7},{%8,%9},{%0,%1,%2,%3};"
        : "+f"(c[0]), "+f"(c[1]), "+f"(c[2]), "+f"(c[3])
        : "r"(a[0]), "r"(a[1]), "r"(a[2]), "r"(a[3]), "r"(b0), "r"(b1));
}

// ---------------- prep: concat weights/biases ----------------
__global__ void k_prep(const float* __restrict__ Wl0, const float* __restrict__ Wr0,
                       const float* __restrict__ bl0, const float* __restrict__ br0,
                       const float* __restrict__ Wl1, const float* __restrict__ Wr1,
                       const float* __restrict__ bl1, const float* __restrict__ br1) {
    int i = blockIdx.x * blockDim.x + threadIdx.x;
    int stride = gridDim.x * blockDim.x;
    for (int idx = i; idx < HID * 2 * HID; idx += stride) {
        int r = idx >> 9, c = idx & 511;
        g_wcat0[idx] = (c < HID) ? Wl0[r * HID + c] : Wr0[r * HID + c - HID];
    }
    for (int idx = i; idx < HID * 2 * DOUT; idx += stride) {
        int r = idx >> 6, c = idx & 63;
        g_wcat1[idx] = (c < DOUT) ? Wl1[r * DOUT + c] : Wr1[r * DOUT + c - DOUT];
    }
    if (i < 2 * HID) g_bcat0[i] = (i < HID) ? bl0[i] : br0[i - HID];
    if (i < 2 * DOUT) g_bcat1[i] = (i < DOUT) ? bl1[i] : br1[i - DOUT];
}

// ---------------- CSR branch: init counts + per-block edge_attr partial sums ----------------
__global__ void k_init_ea(const float* __restrict__ ea) {
    __shared__ float sh[8];
    int i = blockIdx.x * blockDim.x + threadIdx.x;
    int stride = gridDim.x * blockDim.x;
    for (int j = i; j < N_NODES; j += stride) g_count[j] = 1;
    float s = 0.f;
    for (int j = i; j < E_EDGES; j += stride) s += ea[j];
    s = warp_sum(s);
    int lane = threadIdx.x & 31, wid = threadIdx.x >> 5;
    if (lane == 0) sh[wid] = s;
    __syncthreads();
    if (wid == 0) {
        s = (lane < (blockDim.x >> 5)) ? sh[lane] : 0.f;
        s = warp_sum(s);
        if (lane == 0) g_ea_part[blockIdx.x] = s;
    }
}

// ---------------- histogram by dst; atomic return value IS the edge's slot rank ----------------
__global__ void k_hist(const int* __restrict__ ei) {
    int e = blockIdx.x * blockDim.x + threadIdx.x;
    if (e < E_EDGES) {
        int rank = atomicAdd(&g_count[ei[E_EDGES + e]], 1);  // >=1 (slot 0 = self loop)
        g_rank[e] = rank;
    }
}

// ---------------- 1-block scan of offsets + ea-mean reduce ----------------
__global__ void k_scan() {
    __shared__ int warp_tot[32];
    const int t = threadIdx.x;
    const int lane = t & 31, wid = t >> 5;
    const int CH = 10;
    int base = t * CH;
    int local[CH];
    int s = 0;
    #pragma unroll
    for (int i = 0; i < CH; i++) {
        int idx = base + i;
        int v = (idx < N_NODES) ? g_count[idx] : 0;
        local[i] = s;
        s += v;
    }
    int x = s;
    #pragma unroll
    for (int o = 1; o < 32; o <<= 1) {
        int y = __shfl_up_sync(0xffffffffu, x, o);
        if (lane >= o) x += y;
    }
    if (lane == 31) warp_tot[wid] = x;
    __syncthreads();
    if (wid == 0) {
        int w = warp_tot[lane];
        #pragma unroll
        for (int o = 1; o < 32; o <<= 1) {
            int y = __shfl_up_sync(0xffffffffu, w, o);
            if (lane >= o) w += y;
        }
        warp_tot[lane] = w;
    }
    if (wid == 1) {
        float v = g_ea_part[lane] + g_ea_part[lane + 32];
        v = warp_sum(v);
        if (lane == 0) g_ea_mean = v * (1.f / (float)E_EDGES);
    }
    __syncthreads();
    int pre = x - s + (wid > 0 ? warp_tot[wid - 1] : 0);
    #pragma unroll
    for (int i = 0; i < CH; i++) {
        int idx = base + i;
        if (idx <= N_NODES) g_off[idx] = pre + local[i];
    }
}

// ---------------- scatter edges + self loops (no cursor atomics) ----------------
__global__ void k_scatter(const int* __restrict__ ei, const float* __restrict__ eattr) {
    int e = blockIdx.x * blockDim.x + threadIdx.x;
    if (e < E_EDGES) {
        int dst = ei[E_EDGES + e];
        int pos = g_off[dst] + g_rank[e];
        g_edge[pos] = make_int2(ei[e], __float_as_int(eattr[e]));
    } else if (e < E_TOT) {
        int i = e - E_EDGES;
        g_edge[g_off[i]] = make_int2(i, __float_as_int(g_ea_mean));
    }
}

// ---------------- tf32 tensor-core GEMM: C = A[M,K] @ B[K,Nc] + bias ----------------
// SPLIT: cols [0,S) -> C0 (optionally fp16), cols [S,2S) -> C1 (fp32)
template<bool SPLIT, bool HALF0>
__global__ void mma_gemm(const float* __restrict__ A, const float* __restrict__ B,
                         const float* __restrict__ bias,
                         void* __restrict__ C0v, float* __restrict__ C1,
                         int M, int Nc, int K) {
    constexpr int BM = 128, BN = 64, BK = 32;
    constexpr int NT = 256;
    constexpr int NA = BM * BK / 4 / NT;
    constexpr int NB = BK * BN / 4 / NT;
    __shared__ uint32_t As[BM][BK + 4];
    __shared__ uint32_t Bs[BK][BN + 4];

    const int tid = threadIdx.x;
    const int wid = tid >> 5;
    const int lane = tid & 31;
    const int gid = lane >> 2;
    const int tg  = lane & 3;
    const int wm = (wid & 3) * 32;
    const int wn = (wid >> 2) * 32;
    const int row0 = blockIdx.y * BM, col0 = blockIdx.x * BN;

    float acc[2][4][4];
    #pragma unroll
    for (int mt = 0; mt < 2; mt++)
        #pragma unroll
        for (int nt = 0; nt < 4; nt++)
            #pragma unroll
            for (int i = 0; i < 4; i++) acc[mt][nt][i] = 0.f;

    float4 ra[NA], rb[NB];

    auto g2r = [&](int k0) {
        #pragma unroll
        for (int i = 0; i < NA; i++) {
            int lin = (tid + i * NT) * 4;
            int r = lin / BK, c = lin % BK;
            int gr = row0 + r;
            ra[i] = (gr < M) ? *(const float4*)&A[(size_t)gr * K + k0 + c]
                             : make_float4(0.f, 0.f, 0.f, 0.f);
        }
        #pragma unroll
        for (int i = 0; i < NB; i++) {
            int lin = (tid + i * NT) * 4;
            int kr = lin / BN, c = lin % BN;
            rb[i] = *(const float4*)&B[(size_t)(k0 + kr) * Nc + col0 + c];
        }
    };
    auto r2s = [&]() {
        #pragma unroll
        for (int i = 0; i < NA; i++) {
            int lin = (tid + i * NT) * 4;
            int r = lin / BK, c = lin % BK;
            As[r][c + 0] = f2tf32(ra[i].x); As[r][c + 1] = f2tf32(ra[i].y);
            As[r][c + 2] = f2tf32(ra[i].z); As[r][c + 3] = f2tf32(ra[i].w);
        }
        #pragma unroll
        for (int i = 0; i < NB; i++) {
            int lin = (tid + i * NT) * 4;
            int kr = lin / BN, c = lin % BN;
            Bs[kr][c + 0] = f2tf32(rb[i].x); Bs[kr][c + 1] = f2tf32(rb[i].y);
            Bs[kr][c + 2] = f2tf32(rb[i].z); Bs[kr][c + 3] = f2tf32(rb[i].w);
        }
    };

    g2r(0);
    r2s();
    __syncthreads();

    const int NTILES = K / BK;
    for (int t = 0; t < NTILES; t++) {
        if (t + 1 < NTILES) g2r((t + 1) * BK);
        #pragma unroll
        for (int ks = 0; ks < BK; ks += 8) {
            uint32_t af[2][4];
            #pragma unroll
            for (int mt = 0; mt < 2; mt++) {
                int r0 = wm + mt * 16 + gid;
                af[mt][0] = As[r0][ks + tg];
                af[mt][1] = As[r0 + 8][ks + tg];
                af[mt][2] = As[r0][ks + tg + 4];
                af[mt][3] = As[r0 + 8][ks + tg + 4];
            }
            #pragma unroll
            for (int nt = 0; nt < 4; nt++) {
                int cn = wn + nt * 8 + gid;
                uint32_t b0 = Bs[ks + tg][cn];
                uint32_t b1 = Bs[ks + tg + 4][cn];
                #pragma unroll
                for (int mt = 0; mt < 2; mt++)
                    mma_tf32(acc[mt][nt], af[mt], b0, b1);
            }
        }
        if (t + 1 < NTILES) {
            __syncthreads();
            r2s();
            __syncthreads();
        }
    }

    const int S = Nc >> 1;
    #pragma unroll
    for (int mt = 0; mt < 2; mt++) {
        int gr0 = row0 + wm + mt * 16 + gid;
        int gr1 = gr0 + 8;
        #pragma unroll
        for (int nt = 0; nt < 4; nt++) {
            int gc = col0 + wn + nt * 8 + tg * 2;
            float b0 = bias[gc], b1 = bias[gc + 1];
            float v00 = acc[mt][nt][0] + b0, v01 = acc[mt][nt][1] + b1;
            float v10 = acc[mt][nt][2] + b0, v11 = acc[mt][nt][3] + b1;
            if (SPLIT) {
                // gc is even; pair (gc, gc+1) never straddles S (S even)
                if (gc < S) {
                    if (HALF0) {
                        __half* C0h = (__half*)C0v;
                        if (gr0 < M) *(__half2*)&C0h[(size_t)gr0 * S + gc] = __floats2half2_rn(v00, v01);
                        if (gr1 < M) *(__half2*)&C0h[(size_t)gr1 * S + gc] = __floats2half2_rn(v10, v11);
                    } else {
                        float* C0f = (float*)C0v;
                        if (gr0 < M) *(float2*)&C0f[(size_t)gr0 * S + gc] = make_float2(v00, v01);
                        if (gr1 < M) *(float2*)&C0f[(size_t)gr1 * S + gc] = make_float2(v10, v11);
                    }
                } else {
                    if (gr0 < M) *(float2*)&C1[(size_t)gr0 * S + gc - S] = make_float2(v00, v01);
                    if (gr1 < M) *(float2*)&C1[(size_t)gr1 * S + gc - S] = make_float2(v10, v11);
                }
            } else {
                float* C0f = (float*)C0v;
                if (gr0 < M) *(float2*)&C0f[(size_t)gr0 * Nc + gc] = make_float2(v00, v01);
                if (gr1 < M) *(float2*)&C0f[(size_t)gr1 * Nc + gc] = make_float2(v10, v11);
            }
        }
    }
}

// ---------------- fused layer-0: 2 warps per node, fp16 gather + online softmax + smem merge ----------------
__global__ void k_node0(const float* __restrict__ We, const float* __restrict__ att,
                        const float* __restrict__ bias0, const float* __restrict__ g0,
                        const float* __restrict__ be0) {
    __shared__ float smerge[8][32][10];   // [warp][lane][accA4|accB4|m|s]

    const int warp = threadIdx.x >> 5;
    const int lane = threadIdx.x & 31;
    const int r = blockIdx.x * 4 + (warp >> 1);
    const int half = warp & 1;
    const int idx0 = lane * 2, idx1 = lane * 2 + 1;

    const uint4* xlh = (const uint4*)g_xl0h;   // row = 256 half = 32 uint4; lane owns one uint4
    const float4* xr4 = (const float4*)g_xr0;
    const float4* We4 = (const float4*)We;
    const float4* at4 = (const float4*)att;

    float4 xra = xr4[r * 64 + idx0], xrb = xr4[r * 64 + idx1];
    float4 wea = We4[idx0],          web = We4[idx1];
    float4 ata = at4[idx0],          atb = at4[idx1];

    const float NINF = __int_as_float(0xFF800000);
    float m = NINF, s = 0.f;
    float4 accA = make_float4(0.f, 0.f, 0.f, 0.f);
    float4 accB = make_float4(0.f, 0.f, 0.f, 0.f);

    const int beg = g_off[r], end = g_off[r + 1];

    // convert a gathered uint4 (8 halves) into two float4s
    #define CVT8(q, a, b)                                                 \
        do {                                                              \
            float2 f0 = __half22float2(*(const __half2*)&(q).x);          \
            float2 f1 = __half22float2(*(const __half2*)&(q).y);          \
            float2 f2 = __half22float2(*(const __half2*)&(q).z);          \
            float2 f3 = __half22float2(*(const __half2*)&(q).w);          \
            (a) = make_float4(f0.x, f0.y, f1.x, f1.y);                    \
            (b) = make_float4(f2.x, f2.y, f3.x, f3.y);                    \
        } while (0)

    #define LOGIT(a, b, ea)                                              \
        (lrelu((a).x + xra.x + (ea) * wea.x) * ata.x                     \
       + lrelu((a).y + xra.y + (ea) * wea.y) * ata.y                     \
       + lrelu((a).z + xra.z + (ea) * wea.z) * ata.z                     \
       + lrelu((a).w + xra.w + (ea) * wea.w) * ata.w                     \
       + lrelu((b).x + xrb.x + (ea) * web.x) * atb.x                     \
       + lrelu((b).y + xrb.y + (ea) * web.y) * atb.y                     \
       + lrelu((b).z + xrb.z + (ea) * web.z) * atb.z                     \
       + lrelu((b).w + xrb.w + (ea) * web.w) * atb.w)

    #define ONLINE_UPD(p, a, b)                                           \
        do {                                                              \
            if ((p) > m) {                                                \
                float c_ = __expf(m - (p));                               \
                s *= c_;                                                  \
                accA.x *= c_; accA.y *= c_; accA.z *= c_; accA.w *= c_;   \
                accB.x *= c_; accB.y *= c_; accB.z *= c_; accB.w *= c_;   \
                m = (p);                                                  \
            }                                                             \
            float w_ = __expf((p) - m);                                   \
            s += w_;                                                      \
            accA.x += w_ * (a).x; accA.y += w_ * (a).y;                   \
            accA.z += w_ * (a).z; accA.w += w_ * (a).w;                   \
            accB.x += w_ * (b).x; accB.y += w_ * (b).y;                   \
            accB.z += w_ * (b).z; accB.w += w_ * (b).w;                   \
        } while (0)

    int j = beg + half;
    for (; j + 2 < end; j += 4) {   // two edges: j and j+2
        int2 ed0 = g_edge[j], ed1 = g_edge[j + 2];
        float e0 = __int_as_float(ed0.y), e1 = __int_as_float(ed1.y);
        uint4 q0 = xlh[ed0.x * 32 + lane];
        uint4 q1 = xlh[ed1.x * 32 + lane];
        float4 a0, b0, a1, b1;
        CVT8(q0, a0, b0);
        CVT8(q1, a1, b1);

        float p0 = LOGIT(a0, b0, e0);
        float p1 = LOGIT(a1, b1, e1);
        #pragma unroll
        for (int o = 8; o > 0; o >>= 1) {
            p0 += __shfl_xor_sync(0xffffffffu, p0, o);
            p1 += __shfl_xor_sync(0xffffffffu, p1, o);
        }
        ONLINE_UPD(p0, a0, b0);
        ONLINE_UPD(p1, a1, b1);
    }
    if (j < end) {
        int2 ed0 = g_edge[j];
        float e0 = __int_as_float(ed0.y);
        uint4 q0 = xlh[ed0.x * 32 + lane];
        float4 a0, b0;
        CVT8(q0, a0, b0);
        float p0 = LOGIT(a0, b0, e0);
        #pragma unroll
        for (int o = 8; o > 0; o >>= 1) p0 += __shfl_xor_sync(0xffffffffu, p0, o);
        ONLINE_UPD(p0, a0, b0);
    }
    #undef CVT8
    #undef LOGIT
    #undef ONLINE_UPD

    // publish partial state
    float* st = smerge[warp][lane];
    st[0] = accA.x; st[1] = accA.y; st[2] = accA.z; st[3] = accA.w;
    st[4] = accB.x; st[5] = accB.y; st[6] = accB.z; st[7] = accB.w;
    st[8] = m; st[9] = s;
    __syncthreads();
    if (half) return;

    // merge partner state
    {
        const float* pt = smerge[warp + 1][lane];
        float mB = pt[8], sB = pt[9];
        float M = fmaxf(m, mB);
        float cA = __expf(m - M), cB = __expf(mB - M);
        s = s * cA + sB * cB;
        accA.x = accA.x * cA + pt[0] * cB; accA.y = accA.y * cA + pt[1] * cB;
        accA.z = accA.z * cA + pt[2] * cB; accA.w = accA.w * cA + pt[3] * cB;
        accB.x = accB.x * cA + pt[4] * cB; accB.y = accB.y * cA + pt[5] * cB;
        accB.z = accB.z * cA + pt[6] * cB; accB.w = accB.w * cA + pt[7] * cB;
    }

    float inv = 1.f / (s + 1e-16f);

    const float4* b4 = (const float4*)bias0;
    const float4* h4 = (const float4*)g_hidden;
    float4 bia = b4[idx0], bib = b4[idx1];
    float4 ha = h4[r * 64 + idx0], hb = h4[r * 64 + idx1];

    float4 v0, v1;
    v0.x = accA.x * inv + bia.x + ha.x; v0.y = accA.y * inv + bia.y + ha.y;
    v0.z = accA.z * inv + bia.z + ha.z; v0.w = accA.w * inv + bia.w + ha.w;
    v1.x = accB.x * inv + bib.x + hb.x; v1.y = accB.y * inv + bib.y + hb.y;
    v1.z = accB.z * inv + bib.z + hb.z; v1.w = accB.w * inv + bib.w + hb.w;

    float su = v0.x + v0.y + v0.z + v0.w + v1.x + v1.y + v1.z + v1.w;
    float sq = v0.x * v0.x + v0.y * v0.y + v0.z * v0.z + v0.w * v0.w
             + v1.x * v1.x + v1.y * v1.y + v1.z * v1.z + v1.w * v1.w;
    su = warp_sum(su);
    sq = warp_sum(sq);
    float mu = su / 256.f;
    float var = sq / 256.f - mu * mu;
    float rs = rsqrtf(var + 1e-5f);

    const float4* gg4 = (const float4*)g0;
    const float4* bb4 = (const float4*)be0;
    float4 ga = gg4[idx0], gb = gg4[idx1];
    float4 ba = bb4[idx0], bb = bb4[idx1];
    float4* out4 = (float4*)g_h1;
    float4 o0, o1;
    o0.x = fmaxf(0.f, (v0.x - mu) * rs * ga.x + ba.x);
    o0.y = fmaxf(0.f, (v0.y - mu) * rs * ga.y + ba.y);
    o0.z = fmaxf(0.f, (v0.z - mu) * rs * ga.z + ba.z);
    o0.w = fmaxf(0.f, (v0.w - mu) * rs * ga.w + ba.w);
    o1.x = fmaxf(0.f, (v1.x - mu) * rs * gb.x + bb.x);
    o1.y = fmaxf(0.f, (v1.y - mu) * rs * gb.y + bb.y);
    o1.z = fmaxf(0.f, (v1.z - mu) * rs * gb.z + bb.z);
    o1.w = fmaxf(0.f, (v1.w - mu) * rs * gb.w + bb.w);
    out4[r * 64 + idx0] = o0;
    out4[r * 64 + idx1] = o1;
}

// ---------------- fused layer-1: 2 warps per node, online softmax + smem merge ----------------
__global__ void k_node1(const float* __restrict__ We, const float* __restrict__ att,
                        const float* __restrict__ bias1, const float* __restrict__ g1,
                        const float* __restrict__ be1, float* __restrict__ out) {
    __shared__ float smerge[8][32][3];   // [warp][lane][acc|m|s]

    const int warp = threadIdx.x >> 5;
    const int lane = threadIdx.x & 31;
    const int r = blockIdx.x * 4 + (warp >> 1);
    const int half = warp & 1;

    float xr = g_xr1[r * DOUT + lane];
    float we = We[lane];
    float at = att[lane];

    const float NINF = __int_as_float(0xFF800000);
    float m = NINF, s = 0.f, acc = 0.f;

    const int beg = g_off[r], end = g_off[r + 1];

    #define UPD1(p, x)                                                     \
        do {                                                               \
            if ((p) > m) { float c_ = __expf(m - (p)); s *= c_; acc *= c_; m = (p); } \
            float w_ = __expf((p) - m); s += w_; acc += w_ * (x);          \
        } while (0)

    int j = beg + half;
    for (; j + 2 < end; j += 4) {
        int2 ed0 = g_edge[j], ed1 = g_edge[j + 2];
        float e0 = __int_as_float(ed0.y), e1 = __int_as_float(ed1.y);
        float x0 = g_xl1[ed0.x * DOUT + lane];
        float x1 = g_xl1[ed1.x * DOUT + lane];

        float p0 = lrelu(x0 + xr + e0 * we) * at;
        float p1 = lrelu(x1 + xr + e1 * we) * at;
        #pragma unroll
        for (int o = 8; o > 0; o >>= 1) {
            p0 += __shfl_xor_sync(0xffffffffu, p0, o);
            p1 += __shfl_xor_sync(0xffffffffu, p1, o);
        }
        UPD1(p0, x0);
        UPD1(p1, x1);
    }
    if (j < end) {
        int2 ed0 = g_edge[j];
        float e0 = __int_as_float(ed0.y);
        float x0 = g_xl1[ed0.x * DOUT + lane];
        float p0 = lrelu(x0 + xr + e0 * we) * at;
        #pragma unroll
        for (int o = 8; o > 0; o >>= 1) p0 += __shfl_xor_sync(0xffffffffu, p0, o);
        UPD1(p0, x0);
    }
    #undef UPD1

    float* st = smerge[warp][lane];
    st[0] = acc; st[1] = m; st[2] = s;
    __syncthreads();
    if (half) return;

    {
        const float* pt = smerge[warp + 1][lane];
        float mB = pt[1], sB = pt[2];
        float M = fmaxf(m, mB);
        float cA = __expf(m - M), cB = __expf(mB - M);
        s = s * cA + sB * cB;
        acc = acc * cA + pt[0] * cB;
    }

    float t = acc / (s + 1e-16f) + bias1[lane];
    float su = warp_sum(t);
    float sq = warp_sum(t * t);
    float mu = su / 32.f;
    float var = sq / 32.f - mu * mu;
    float rs = rsqrtf(var + 1e-5f);
    out[r * DOUT + lane] = fmaxf(0.f, (t - mu) * rs * g1[lane] + be1[lane]);
}

// ---------------- launch ----------------
extern "C" void kernel_launch(void* const* d_in, const int* in_sizes, int n_in,
                              void* d_out, int out_size) {
    const float* x     = (const float*)d_in[0];
    const int*   ei    = (const int*)d_in[1];
    const float* eattr = (const float*)d_in[2];
    const float* Wp    = (const float*)d_in[3];
    const float* bp    = (const float*)d_in[4];
    const float* Wl0   = (const float*)d_in[5];
    const float* bl0   = (const float*)d_in[6];
    const float* Wr0   = (const float*)d_in[7];
    const float* br0   = (const float*)d_in[8];
    const float* We0   = (const float*)d_in[9];
    const float* att0  = (const float*)d_in[10];
    const float* bias0 = (const float*)d_in[11];
    const float* g0    = (const float*)d_in[12];
    const float* be0   = (const float*)d_in[13];
    const float* Wl1   = (const float*)d_in[14];
    const float* bl1   = (const float*)d_in[15];
    const float* Wr1   = (const float*)d_in[16];
    const float* br1   = (const float*)d_in[17];
    const float* We1   = (const float*)d_in[18];
    const float* att1  = (const float*)d_in[19];
    const float* bias1 = (const float*)d_in[20];
    const float* g1    = (const float*)d_in[21];
    const float* be1   = (const float*)d_in[22];
    float* out = (float*)d_out;

    float *hidden, *xr0, *h1, *xl1, *xr1, *wcat0, *wcat1, *bcat0, *bcat1;
    __half* xl0h;
    cudaGetSymbolAddress((void**)&hidden, g_hidden);
    cudaGetSymbolAddress((void**)&xl0h, g_xl0h);
    cudaGetSymbolAddress((void**)&xr0, g_xr0);
    cudaGetSymbolAddress((void**)&h1, g_h1);
    cudaGetSymbolAddress((void**)&xl1, g_xl1);
    cudaGetSymbolAddress((void**)&xr1, g_xr1);
    cudaGetSymbolAddress((void**)&wcat0, g_wcat0);
    cudaGetSymbolAddress((void**)&wcat1, g_wcat1);
    cudaGetSymbolAddress((void**)&bcat0, g_bcat0);
    cudaGetSymbolAddress((void**)&bcat1, g_bcat1);

    // ---- fork: CSR branch on g_sh.s, prep on g_sh.s2, GEMMs on stream 0 ----
    cudaEventRecord(g_sh.ef, 0);
    cudaStreamWaitEvent(g_sh.s, g_sh.ef, 0);
    cudaStreamWaitEvent(g_sh.s2, g_sh.ef, 0);

    // CSR branch (4 kernels)
    k_init_ea<<<64, 256, 0, g_sh.s>>>(eattr);
    k_hist<<<(E_EDGES + 255) / 256, 256, 0, g_sh.s>>>(ei);
    k_scan<<<1, 1024, 0, g_sh.s>>>();
    k_scatter<<<(E_TOT + 255) / 256, 256, 0, g_sh.s>>>(ei, eattr);
    cudaEventRecord(g_sh.ej, g_sh.s);

    // prep branch
    k_prep<<<256, 256, 0, g_sh.s2>>>(Wl0, Wr0, bl0, br0, Wl1, Wr1, bl1, br1);
    cudaEventRecord(g_sh.ep, g_sh.s2);

    // GEMM branch (stream 0)
    {
        dim3 grid(256 / 64, (N_NODES + 127) / 128);
        mma_gemm<false, false><<<grid, 256>>>(x, Wp, bp, hidden, nullptr, N_NODES, 256, 512);
    }
    cudaStreamWaitEvent(0, g_sh.ep, 0);
    {
        dim3 grid(512 / 64, (N_NODES + 127) / 128);
        mma_gemm<true, true><<<grid, 256>>>(hidden, wcat0, bcat0, xl0h, xr0, N_NODES, 512, HID);
    }

    // ---- join: k_node0 needs CSR + xl0h/xr0 ----
    cudaStreamWaitEvent(0, g_sh.ej, 0);

    k_node0<<<N_NODES / 4, 256>>>(We0, att0, bias0, g0, be0);

    {
        dim3 grid(64 / 64, (N_NODES + 127) / 128);
        mma_gemm<true, false><<<grid, 256>>>(h1, wcat1, bcat1, xl1, xr1, N_NODES, 64, HID);
    }

    k_node1<<<N_NODES / 4, 256>>>(We1, att1, bias1, g1, be1, out);
}